// round 12
// baseline (speedup 1.0000x reference)
#include <cuda_runtime.h>
#include <cuda_bf16.h>
#include <cstdint>

#define H 27
#define T_STEPS 78
#define THREADS 256
#define NT_GATE 14

// ---- SMEM layout (bytes) ----
// A: [128 rows][8 slices x 32 bf16] = 512B/row, padded to 528B
//    slices: 0 xH, 1 xL, 2 h0H, 3 h0L, 4 h1H, 5 h1L, 6 h2H, 7 h2L
// B1: [3 layers][112 n][4 slices x 32 k bf16] = 256B/row padded to 272B
//    k-slices: 0 WihH(+biasH@k27), 1 WihL(+biasL@k27), 2 WhhH, 3 WhhL
// B2: [32 n][2 slices x 32 k bf16] = 128B/row padded to 144B  (WlH+blH@27 | WlL+blL@27)
#define A_STRIDE   528
#define SM_A       0
#define A_BYTES    (128 * A_STRIDE)          // 67584
#define B1_STRIDE  272
#define B1_LAYER   (112 * B1_STRIDE)          // 30464
#define SM_B1      A_BYTES
#define B2_STRIDE  144
#define SM_B2      (SM_B1 + 3 * B1_LAYER)     // 158976
#define SMEM_TOTAL (SM_B2 + 32 * B2_STRIDE)   // 163584

static __device__ __forceinline__ uint32_t smaddr(const void* p) {
    uint32_t a;
    asm("{ .reg .u64 t; cvta.to.shared.u64 t, %1; cvt.u32.u64 %0, t; }" : "=r"(a) : "l"(p));
    return a;
}
static __device__ __forceinline__ void ldsm_x4(uint32_t addr, uint32_t r[4]) {
    asm volatile("ldmatrix.sync.aligned.m8n8.x4.shared.b16 {%0,%1,%2,%3}, [%4];"
                 : "=r"(r[0]), "=r"(r[1]), "=r"(r[2]), "=r"(r[3]) : "r"(addr));
}
static __device__ __forceinline__ void mma16816(float d[4], const uint32_t a[4],
                                                const uint32_t b0, const uint32_t b1) {
    asm volatile(
        "mma.sync.aligned.m16n8k16.row.col.f32.bf16.bf16.f32 "
        "{%0,%1,%2,%3}, {%4,%5,%6,%7}, {%8,%9}, {%0,%1,%2,%3};"
        : "+f"(d[0]), "+f"(d[1]), "+f"(d[2]), "+f"(d[3])
        : "r"(a[0]), "r"(a[1]), "r"(a[2]), "r"(a[3]), "r"(b0), "r"(b1));
}
static __device__ __forceinline__ uint32_t bfpack(__nv_bfloat16 a, __nv_bfloat16 b) {
    return (uint32_t)__bfloat16_as_ushort(a) | ((uint32_t)__bfloat16_as_ushort(b) << 16);
}
__device__ __forceinline__ float fast_sigmoid(float z) {
    return __fdividef(1.0f, 1.0f + __expf(-z));
}
__device__ __forceinline__ float fast_tanh(float z) {
    return 1.0f - 2.0f * __fdividef(1.0f, __expf(2.0f * z) + 1.0f);
}

// store one half-row (14 cols) into hi/lo slices; col 27 forced to 1.0 (lo=0)
static __device__ __forceinline__ void store_half(char* smem, int row, int half,
                                                  int sliceH, const float* v) {
    const int cbase = half * 14;
    char* base = smem + SM_A + row * A_STRIDE;
    #pragma unroll
    for (int p = 0; p < 7; p++) {
        int c = cbase + 2 * p;
        float v0 = v[2 * p];
        float v1 = (c + 1 == 27) ? 1.0f : v[2 * p + 1];
        __nv_bfloat16 h0 = __float2bfloat16_rn(v0);
        __nv_bfloat16 h1 = __float2bfloat16_rn(v1);
        __nv_bfloat16 l0 = __float2bfloat16_rn(v0 - __bfloat162float(h0));
        __nv_bfloat16 l1 = __float2bfloat16_rn(v1 - __bfloat162float(h1));
        *(uint32_t*)(base + (sliceH * 32 + c) * 2)       = bfpack(h0, h1);
        *(uint32_t*)(base + ((sliceH + 1) * 32 + c) * 2) = bfpack(l0, l1);
    }
}

extern __shared__ char smem[];

__global__ void __launch_bounds__(THREADS, 1)
lstm3_hmma_kernel(const float* __restrict__ x,
                  const float* __restrict__ h0g,
                  const float* __restrict__ c0g,
                  const float* __restrict__ Wih,
                  const float* __restrict__ Whh,
                  const float* __restrict__ bih,
                  const float* __restrict__ bhh,
                  const float* __restrict__ Wl,
                  const float* __restrict__ bl,
                  float* __restrict__ out,
                  int B)
{
    const uint32_t sb = smaddr(smem);
    const int tid  = threadIdx.x;
    const int warp = tid >> 5;
    const int lane = tid & 31;
    const int g8   = lane >> 2;
    const int tq   = lane & 3;
    const int cta_base = blockIdx.x * 128;

    // ---- zero all SMEM ----
    for (int i = tid; i < SMEM_TOTAL / 16; i += THREADS)
        ((uint4*)smem)[i] = make_uint4(0, 0, 0, 0);
    __syncthreads();

    // ---- stage B1 ----
    for (int idx = tid; idx < 3 * 112 * 128; idx += THREADS) {
        int l = idx / (112 * 128);
        int r = idx % (112 * 128);
        int n = r >> 7, k = r & 127;
        int sl = k >> 5, kp = k & 31;
        int j = n >> 2, g = n & 3;
        float w = 0.0f;
        if (j < H) {
            bool isW = (sl < 2);
            if (kp < H) w = (isW ? Wih : Whh)[((size_t)l * 108 + g * H + j) * H + kp];
            else if (kp == H && isW)
                w = bih[(size_t)l * 108 + g * H + j] + bhh[(size_t)l * 108 + g * H + j];
        }
        __nv_bfloat16 hi = __float2bfloat16_rn(w);
        __nv_bfloat16 v = (sl & 1) ? __float2bfloat16_rn(w - __bfloat162float(hi)) : hi;
        *(__nv_bfloat16*)(smem + SM_B1 + l * B1_LAYER + n * B1_STRIDE + k * 2) = v;
    }
    // ---- stage B2 ----
    for (int idx = tid; idx < 32 * 64; idx += THREADS) {
        int n = idx >> 6, k = idx & 63;
        int sl = k >> 5, kp = k & 31;
        float w = 0.0f;
        if (n < H) {
            if (kp < H) w = Wl[n * H + kp];
            else if (kp == H) w = bl[n];
        }
        __nv_bfloat16 hi = __float2bfloat16_rn(w);
        __nv_bfloat16 v = sl ? __float2bfloat16_rn(w - __bfloat162float(hi)) : hi;
        *(__nv_bfloat16*)(smem + SM_B2 + n * B2_STRIDE + k * 2) = v;
    }

    // ---- stage A init: x(0), h0/h1/h2 ----
    {
        int row = tid >> 1, half = tid & 1;
        float v[14];
        const float* xs = x + ((size_t)(cta_base + row) * T_STEPS + 0) * H + half * 14;
        #pragma unroll
        for (int i = 0; i < 14; i++) v[i] = (half && i == 13) ? 0.0f : xs[i];
        store_half(smem, row, half, 0, v);
        #pragma unroll
        for (int l = 0; l < 3; l++) {
            const float* hs = h0g + ((size_t)l * B + cta_base + row) * H + half * 14;
            #pragma unroll
            for (int i = 0; i < 14; i++) v[i] = (half && i == 13) ? 0.0f : hs[i];
            store_half(smem, row, half, 2 + 2 * l, v);
        }
    }
    __syncthreads();

    // ---- c state in registers ----
    float cst[3][14];
    #pragma unroll
    for (int l = 0; l < 3; l++)
        #pragma unroll
        for (int p = 0; p < 7; p++) {
            int nt = 2 * p + (tq & 1);
            int j = 2 * nt + (tq >> 1);
            int r0 = 16 * warp + g8;
            if (j < H) {
                cst[l][2*p]   = c0g[((size_t)l * B + cta_base + r0)     * H + j];
                cst[l][2*p+1] = c0g[((size_t)l * B + cta_base + r0 + 8) * H + j];
            } else {
                cst[l][2*p] = 0.0f; cst[l][2*p+1] = 0.0f;
            }
        }

    // mma schedules
    const int AS[12] = {0,1,0,1,2,3,4,5,4,5,6,7};
    const int BS[12] = {0,1,2,3,0,1,4,5,6,7,4,5};

    // A-ldmatrix lane addressing
    const int arow = 16 * warp + (lane & 15);
    const uint32_t aoff = sb + SM_A + arow * A_STRIDE + ((lane >> 4) & 1) * 16;
    // B-ldmatrix lane addressing pieces
    const int brr = lane & 7;
    const int bm  = lane >> 3;

    const int prow  = 16 * warp + (lane >> 1);
    const int phalf = lane & 1;

    for (int t = 0; t < T_STEPS; t++) {
        // prefetch x(t+1)
        float xpre[14];
        if (t + 1 < T_STEPS) {
            const float* xs = x + ((size_t)(cta_base + prow) * T_STEPS + t + 1) * H + phalf * 14;
            #pragma unroll
            for (int i = 0; i < 14; i++) xpre[i] = (phalf && i == 13) ? 0.0f : xs[i];
        }

        #pragma unroll
        for (int l = 0; l < 3; l++) {
            __syncwarp();
            // load 8 A frags: slices 2l..2l+3, frags at byte offsets 2l*64 + f*32
            uint32_t af[8][4];
            #pragma unroll
            for (int f = 0; f < 8; f++)
                ldsm_x4(aoff + 2 * l * 64 + f * 32, af[f]);

            #pragma unroll
            for (int nt = 0; nt < NT_GATE; nt++) {
                // load 8 B frags (4 x ldmatrix.x4)
                uint32_t bfr[8][2];
                uint32_t bbase = sb + SM_B1 + l * B1_LAYER + (8 * nt + brr) * B1_STRIDE + bm * 16;
                #pragma unroll
                for (int q = 0; q < 4; q++) {
                    uint32_t r4[4];
                    ldsm_x4(bbase + q * 64, r4);
                    bfr[2*q][0] = r4[0]; bfr[2*q][1] = r4[1];
                    bfr[2*q+1][0] = r4[2]; bfr[2*q+1][1] = r4[3];
                }
                float d[4] = {0.f, 0.f, 0.f, 0.f};
                #pragma unroll
                for (int s = 0; s < 12; s++)
                    mma16816(d, af[AS[s]], bfr[BS[s]][0], bfr[BS[s]][1]);

                // ---- epilogue for this n-tile ----
                float s0, s1, s2, s3;
                if (tq & 1) {
                    s0 = fast_tanh(d[0]);    s1 = fast_sigmoid(d[1]);
                    s2 = fast_tanh(d[2]);    s3 = fast_sigmoid(d[3]);
                } else {
                    s0 = fast_sigmoid(d[0]); s1 = fast_sigmoid(d[1]);
                    s2 = fast_sigmoid(d[2]); s3 = fast_sigmoid(d[3]);
                }
                float o0 = __shfl_xor_sync(0xffffffffu, s0, 1);
                float o1 = __shfl_xor_sync(0xffffffffu, s1, 1);
                float o2 = __shfl_xor_sync(0xffffffffu, s2, 1);
                float o3 = __shfl_xor_sync(0xffffffffu, s3, 1);
                const int j = 2 * nt + (tq >> 1);
                const bool own = (((nt ^ tq) & 1) == 0);
                if (own && j < H) {
                    float iv0, fv0, gv0, ov0, iv1, fv1, gv1, ov1;
                    if (tq & 1) { iv0=o0; fv0=o1; gv0=s0; ov0=s1; iv1=o2; fv1=o3; gv1=s2; ov1=s3; }
                    else        { iv0=s0; fv0=s1; gv0=o0; ov0=o1; iv1=s2; fv1=s3; gv1=o2; ov1=o3; }
                    const int p2 = (nt >> 1) * 2;
                    float cn0 = fmaf(fv0, cst[l][p2],     iv0 * gv0); cst[l][p2]     = cn0;
                    float cn1 = fmaf(fv1, cst[l][p2 + 1], iv1 * gv1); cst[l][p2 + 1] = cn1;
                    float hv0 = ov0 * fast_tanh(cn0);
                    float hv1 = ov1 * fast_tanh(cn1);
                    __nv_bfloat16 h0b = __float2bfloat16_rn(hv0);
                    __nv_bfloat16 l0b = __float2bfloat16_rn(hv0 - __bfloat162float(h0b));
                    __nv_bfloat16 h1b = __float2bfloat16_rn(hv1);
                    __nv_bfloat16 l1b = __float2bfloat16_rn(hv1 - __bfloat162float(h1b));
                    char* b0p = smem + SM_A + (16 * warp + g8)     * A_STRIDE;
                    char* b1p = smem + SM_A + (16 * warp + g8 + 8) * A_STRIDE;
                    const int offH = ((2 * l + 2) * 32 + j) * 2;
                    const int offL = ((2 * l + 3) * 32 + j) * 2;
                    *(__nv_bfloat16*)(b0p + offH) = h0b;
                    *(__nv_bfloat16*)(b0p + offL) = l0b;
                    *(__nv_bfloat16*)(b1p + offH) = h1b;
                    *(__nv_bfloat16*)(b1p + offL) = l1b;
                }
            }
            // stage x(t+1) after layer-0 consumed the x slice
            if (l == 0 && t + 1 < T_STEPS)
                store_half(smem, prow, phalf, 0, xpre);
        }

        // ---- final linear ----
        __syncwarp();
        uint32_t aff[4][4];
        #pragma unroll
        for (int f = 0; f < 4; f++)
            ldsm_x4(aoff + 6 * 64 + f * 32, aff[f]);
        #pragma unroll
        for (int nt = 0; nt < 4; nt++) {
            uint32_t bfr[4][2];
            uint32_t bbase = sb + SM_B2 + (8 * nt + brr) * B2_STRIDE + bm * 16;
            #pragma unroll
            for (int q = 0; q < 2; q++) {
                uint32_t r4[4];
                ldsm_x4(bbase + q * 64, r4);
                bfr[2*q][0] = r4[0]; bfr[2*q][1] = r4[1];
                bfr[2*q+1][0] = r4[2]; bfr[2*q+1][1] = r4[3];
            }
            float d[4] = {0.f, 0.f, 0.f, 0.f};
            mma16816(d, aff[0], bfr[0][0], bfr[0][1]);
            mma16816(d, aff[1], bfr[1][0], bfr[1][1]);
            mma16816(d, aff[0], bfr[2][0], bfr[2][1]);
            mma16816(d, aff[1], bfr[3][0], bfr[3][1]);
            mma16816(d, aff[2], bfr[0][0], bfr[0][1]);
            mma16816(d, aff[3], bfr[1][0], bfr[1][1]);
            const int col = 8 * nt + 2 * tq;
            if (col < H) {
                const int rg = cta_base + 16 * warp + g8;
                float* p0 = out + ((size_t)rg * T_STEPS + t) * H + col;
                float* p1 = out + ((size_t)(rg + 8) * T_STEPS + t) * H + col;
                p0[0] = d[0];
                p1[0] = d[2];
                if (col + 1 < H) { p0[1] = d[1]; p1[1] = d[3]; }
            }
        }
    }
}

extern "C" void kernel_launch(void* const* d_in, const int* in_sizes, int n_in,
                              void* d_out, int out_size)
{
    const float* x   = (const float*)d_in[0];
    const float* h0  = (const float*)d_in[1];
    const float* c0  = (const float*)d_in[2];
    const float* Wih = (const float*)d_in[3];
    const float* Whh = (const float*)d_in[4];
    const float* bih = (const float*)d_in[5];
    const float* bhh = (const float*)d_in[6];
    const float* Wl  = (const float*)d_in[7];
    const float* bl  = (const float*)d_in[8];
    float* out = (float*)d_out;

    const int B = in_sizes[0] / (T_STEPS * H);   // 32768

    static bool attr_set = false;
    if (!attr_set) {
        cudaFuncSetAttribute(lstm3_hmma_kernel,
                             cudaFuncAttributeMaxDynamicSharedMemorySize, SMEM_TOTAL);
        attr_set = true;
    }

    const int grid = (B + 127) / 128;   // 256
    lstm3_hmma_kernel<<<grid, THREADS, SMEM_TOTAL>>>(
        x, h0, c0, Wih, Whh, bih, bhh, Wl, bl, out, B);
}

// round 14
// speedup vs baseline: 1.4409x; 1.4409x over previous
#include <cuda_runtime.h>
#include <cuda_bf16.h>
#include <cstdint>

#define H 27
#define T_STEPS 78
#define THREADS 448
#define NWARPS 14
#define ROWS_CTA 224
#define NT_GATE 14

// ---- SMEM layout (bytes) ----
// A: [224 rows][8 slices x 32 bf16] = 512B/row, padded to 528B
//    slices: 0 xH, 1 xL, 2 h0H, 3 h0L, 4 h1H, 5 h1L, 6 h2H, 7 h2L
// B1: [3 layers][112 n][4 slices x 32 k bf16] = 256B/row padded to 272B
// B2: [32 n][2 slices x 32 k bf16] = 128B/row padded to 144B
#define A_STRIDE   528
#define SM_A       0
#define A_BYTES    (ROWS_CTA * A_STRIDE)      // 118272
#define B1_STRIDE  272
#define B1_LAYER   (112 * B1_STRIDE)          // 30464
#define SM_B1      A_BYTES
#define B2_STRIDE  144
#define SM_B2      (SM_B1 + 3 * B1_LAYER)     // 209664
#define SMEM_TOTAL (SM_B2 + 32 * B2_STRIDE)   // 214272

static __device__ __forceinline__ uint32_t smaddr(const void* p) {
    uint32_t a;
    asm("{ .reg .u64 t; cvta.to.shared.u64 t, %1; cvt.u32.u64 %0, t; }" : "=r"(a) : "l"(p));
    return a;
}
static __device__ __forceinline__ void ldsm_x4(uint32_t addr, uint32_t r[4]) {
    asm volatile("ldmatrix.sync.aligned.m8n8.x4.shared.b16 {%0,%1,%2,%3}, [%4];"
                 : "=r"(r[0]), "=r"(r[1]), "=r"(r[2]), "=r"(r[3]) : "r"(addr));
}
static __device__ __forceinline__ void mma16816(float d[4], const uint32_t a[4],
                                                const uint32_t b0, const uint32_t b1) {
    asm volatile(
        "mma.sync.aligned.m16n8k16.row.col.f32.bf16.bf16.f32 "
        "{%0,%1,%2,%3}, {%4,%5,%6,%7}, {%8,%9}, {%0,%1,%2,%3};"
        : "+f"(d[0]), "+f"(d[1]), "+f"(d[2]), "+f"(d[3])
        : "r"(a[0]), "r"(a[1]), "r"(a[2]), "r"(a[3]), "r"(b0), "r"(b1));
}
static __device__ __forceinline__ uint32_t bfpack(__nv_bfloat16 a, __nv_bfloat16 b) {
    return (uint32_t)__bfloat16_as_ushort(a) | ((uint32_t)__bfloat16_as_ushort(b) << 16);
}
__device__ __forceinline__ float fast_sigmoid(float z) {
    return __fdividef(1.0f, 1.0f + __expf(-z));
}
__device__ __forceinline__ float fast_tanh(float z) {
    return 1.0f - 2.0f * __fdividef(1.0f, __expf(2.0f * z) + 1.0f);
}

// store one half-row (14 cols) into hi/lo slices; col 27 forced to 1.0 (lo=0)
static __device__ __forceinline__ void store_half(char* smem, int row, int half,
                                                  int sliceH, const float* v) {
    const int cbase = half * 14;
    char* base = smem + SM_A + row * A_STRIDE;
    #pragma unroll
    for (int p = 0; p < 7; p++) {
        int c = cbase + 2 * p;
        float v0 = v[2 * p];
        float v1 = (c + 1 == 27) ? 1.0f : v[2 * p + 1];
        __nv_bfloat16 h0 = __float2bfloat16_rn(v0);
        __nv_bfloat16 h1 = __float2bfloat16_rn(v1);
        __nv_bfloat16 l0 = __float2bfloat16_rn(v0 - __bfloat162float(h0));
        __nv_bfloat16 l1 = __float2bfloat16_rn(v1 - __bfloat162float(h1));
        *(uint32_t*)(base + (sliceH * 32 + c) * 2)       = bfpack(h0, h1);
        *(uint32_t*)(base + ((sliceH + 1) * 32 + c) * 2) = bfpack(l0, l1);
    }
}

extern __shared__ char smem[];

__global__ void __launch_bounds__(THREADS, 1)
lstm3_hmma_kernel(const float* __restrict__ x,
                  const float* __restrict__ h0g,
                  const float* __restrict__ c0g,
                  const float* __restrict__ Wih,
                  const float* __restrict__ Whh,
                  const float* __restrict__ bih,
                  const float* __restrict__ bhh,
                  const float* __restrict__ Wl,
                  const float* __restrict__ bl,
                  float* __restrict__ out,
                  int B)
{
    const uint32_t sb = smaddr(smem);
    const int tid  = threadIdx.x;
    const int warp = tid >> 5;
    const int lane = tid & 31;
    const int g8   = lane >> 2;
    const int tq   = lane & 3;
    const int cta_base = blockIdx.x * ROWS_CTA;

    // ---- zero all SMEM ----
    for (int i = tid; i < SMEM_TOTAL / 16; i += THREADS)
        ((uint4*)smem)[i] = make_uint4(0, 0, 0, 0);
    __syncthreads();

    // ---- stage B1 ----
    for (int idx = tid; idx < 3 * 112 * 128; idx += THREADS) {
        int l = idx / (112 * 128);
        int r = idx % (112 * 128);
        int n = r >> 7, k = r & 127;
        int sl = k >> 5, kp = k & 31;
        int j = n >> 2, g = n & 3;
        float w = 0.0f;
        if (j < H) {
            bool isW = (sl < 2);
            if (kp < H) w = (isW ? Wih : Whh)[((size_t)l * 108 + g * H + j) * H + kp];
            else if (kp == H && isW)
                w = bih[(size_t)l * 108 + g * H + j] + bhh[(size_t)l * 108 + g * H + j];
        }
        __nv_bfloat16 hi = __float2bfloat16_rn(w);
        __nv_bfloat16 v = (sl & 1) ? __float2bfloat16_rn(w - __bfloat162float(hi)) : hi;
        *(__nv_bfloat16*)(smem + SM_B1 + l * B1_LAYER + n * B1_STRIDE + k * 2) = v;
    }
    // ---- stage B2 ----
    for (int idx = tid; idx < 32 * 64; idx += THREADS) {
        int n = idx >> 6, k = idx & 63;
        int sl = k >> 5, kp = k & 31;
        float w = 0.0f;
        if (n < H) {
            if (kp < H) w = Wl[n * H + kp];
            else if (kp == H) w = bl[n];
        }
        __nv_bfloat16 hi = __float2bfloat16_rn(w);
        __nv_bfloat16 v = sl ? __float2bfloat16_rn(w - __bfloat162float(hi)) : hi;
        *(__nv_bfloat16*)(smem + SM_B2 + n * B2_STRIDE + k * 2) = v;
    }

    // ---- stage A init: x(0), h0/h1/h2 (guarded for tail CTA) ----
    {
        int row = tid >> 1, half = tid & 1;
        const bool valid = (cta_base + row) < B;
        float v[14];
        const float* xs = x + ((size_t)(cta_base + row) * T_STEPS + 0) * H + half * 14;
        #pragma unroll
        for (int i = 0; i < 14; i++)
            v[i] = (valid && !(half && i == 13)) ? xs[i] : 0.0f;
        store_half(smem, row, half, 0, v);
        #pragma unroll
        for (int l = 0; l < 3; l++) {
            const float* hs = h0g + ((size_t)l * B + cta_base + row) * H + half * 14;
            #pragma unroll
            for (int i = 0; i < 14; i++)
                v[i] = (valid && !(half && i == 13)) ? hs[i] : 0.0f;
            store_half(smem, row, half, 2 + 2 * l, v);
        }
    }
    __syncthreads();

    // ---- c state in registers (guarded) ----
    float cst[3][14];
    #pragma unroll
    for (int l = 0; l < 3; l++)
        #pragma unroll
        for (int p = 0; p < 7; p++) {
            int nt = 2 * p + (tq & 1);
            int j = 2 * nt + (tq >> 1);
            int r0 = cta_base + 16 * warp + g8;
            cst[l][2*p]   = (j < H && r0     < B) ? c0g[((size_t)l * B + r0)     * H + j] : 0.0f;
            cst[l][2*p+1] = (j < H && r0 + 8 < B) ? c0g[((size_t)l * B + r0 + 8) * H + j] : 0.0f;
        }

    // mma schedules: x-chain (frags of slices 2l,2l+1) then h-chain
    const int ASX[6] = {0,1,0,1,2,3};
    const int BSX[6] = {0,1,2,3,0,1};
    const int ASH[6] = {4,5,4,5,6,7};
    const int BSH[6] = {4,5,6,7,4,5};

    // A-ldmatrix lane addressing
    const int arow = 16 * warp + (lane & 15);
    const uint32_t aoff = sb + SM_A + arow * A_STRIDE + ((lane >> 4) & 1) * 16;
    // B-ldmatrix lane addressing pieces
    const int brr = lane & 7;
    const int bm  = lane >> 3;

    const int prow  = 16 * warp + (lane >> 1);
    const int phalf = lane & 1;
    const bool pvalid = (cta_base + prow) < B;

    for (int t = 0; t < T_STEPS; t++) {
        // prefetch x(t+1)
        float xpre[14];
        if (t + 1 < T_STEPS) {
            const float* xs = x + ((size_t)(cta_base + prow) * T_STEPS + t + 1) * H + phalf * 14;
            #pragma unroll
            for (int i = 0; i < 14; i++)
                xpre[i] = (pvalid && !(phalf && i == 13)) ? xs[i] : 0.0f;
        }

        #pragma unroll
        for (int l = 0; l < 3; l++) {
            __syncwarp();
            // load 8 A frags: slices 2l..2l+3
            uint32_t af[8][4];
            #pragma unroll
            for (int f = 0; f < 8; f++)
                ldsm_x4(aoff + 2 * l * 64 + f * 32, af[f]);

            #pragma unroll
            for (int nt = 0; nt < NT_GATE; nt++) {
                uint32_t bfr[8][2];
                uint32_t bbase = sb + SM_B1 + l * B1_LAYER + (8 * nt + brr) * B1_STRIDE + bm * 16;
                #pragma unroll
                for (int q = 0; q < 4; q++) {
                    uint32_t r4[4];
                    ldsm_x4(bbase + q * 64, r4);
                    bfr[2*q][0] = r4[0]; bfr[2*q][1] = r4[1];
                    bfr[2*q+1][0] = r4[2]; bfr[2*q+1][1] = r4[3];
                }
                // dual accumulator chains (x terms | h terms)
                float dx[4] = {0.f, 0.f, 0.f, 0.f};
                float dh[4] = {0.f, 0.f, 0.f, 0.f};
                #pragma unroll
                for (int s = 0; s < 6; s++) {
                    mma16816(dx, af[ASX[s]], bfr[BSX[s]][0], bfr[BSX[s]][1]);
                    mma16816(dh, af[ASH[s]], bfr[BSH[s]][0], bfr[BSH[s]][1]);
                }
                float d[4];
                #pragma unroll
                for (int i = 0; i < 4; i++) d[i] = dx[i] + dh[i];

                // ---- epilogue for this n-tile ----
                float s0, s1, s2, s3;
                if (tq & 1) {
                    s0 = fast_tanh(d[0]);    s1 = fast_sigmoid(d[1]);
                    s2 = fast_tanh(d[2]);    s3 = fast_sigmoid(d[3]);
                } else {
                    s0 = fast_sigmoid(d[0]); s1 = fast_sigmoid(d[1]);
                    s2 = fast_sigmoid(d[2]); s3 = fast_sigmoid(d[3]);
                }
                float o0 = __shfl_xor_sync(0xffffffffu, s0, 1);
                float o1 = __shfl_xor_sync(0xffffffffu, s1, 1);
                float o2 = __shfl_xor_sync(0xffffffffu, s2, 1);
                float o3 = __shfl_xor_sync(0xffffffffu, s3, 1);
                const int j = 2 * nt + (tq >> 1);
                const bool own = (((nt ^ tq) & 1) == 0);
                if (own && j < H) {
                    float iv0, fv0, gv0, ov0, iv1, fv1, gv1, ov1;
                    if (tq & 1) { iv0=o0; fv0=o1; gv0=s0; ov0=s1; iv1=o2; fv1=o3; gv1=s2; ov1=s3; }
                    else        { iv0=s0; fv0=s1; gv0=o0; ov0=o1; iv1=s2; fv1=s3; gv1=o2; ov1=o3; }
                    const int p2 = (nt >> 1) * 2;
                    float cn0 = fmaf(fv0, cst[l][p2],     iv0 * gv0); cst[l][p2]     = cn0;
                    float cn1 = fmaf(fv1, cst[l][p2 + 1], iv1 * gv1); cst[l][p2 + 1] = cn1;
                    float hv0 = ov0 * fast_tanh(cn0);
                    float hv1 = ov1 * fast_tanh(cn1);
                    __nv_bfloat16 h0b = __float2bfloat16_rn(hv0);
                    __nv_bfloat16 l0b = __float2bfloat16_rn(hv0 - __bfloat162float(h0b));
                    __nv_bfloat16 h1b = __float2bfloat16_rn(hv1);
                    __nv_bfloat16 l1b = __float2bfloat16_rn(hv1 - __bfloat162float(h1b));
                    char* b0p = smem + SM_A + (16 * warp + g8)     * A_STRIDE;
                    char* b1p = smem + SM_A + (16 * warp + g8 + 8) * A_STRIDE;
                    const int offH = ((2 * l + 2) * 32 + j) * 2;
                    const int offL = ((2 * l + 3) * 32 + j) * 2;
                    *(__nv_bfloat16*)(b0p + offH) = h0b;
                    *(__nv_bfloat16*)(b0p + offL) = l0b;
                    *(__nv_bfloat16*)(b1p + offH) = h1b;
                    *(__nv_bfloat16*)(b1p + offL) = l1b;
                }
            }
            // stage x(t+1) after layer-0 consumed the x slice
            if (l == 0 && t + 1 < T_STEPS)
                store_half(smem, prow, phalf, 0, xpre);
        }

        // ---- final linear ----
        __syncwarp();
        uint32_t aff[4][4];
        #pragma unroll
        for (int f = 0; f < 4; f++)
            ldsm_x4(aoff + 6 * 64 + f * 32, aff[f]);
        #pragma unroll
        for (int nt = 0; nt < 4; nt++) {
            uint32_t bfr[4][2];
            uint32_t bbase = sb + SM_B2 + (8 * nt + brr) * B2_STRIDE + bm * 16;
            #pragma unroll
            for (int q = 0; q < 2; q++) {
                uint32_t r4[4];
                ldsm_x4(bbase + q * 64, r4);
                bfr[2*q][0] = r4[0]; bfr[2*q][1] = r4[1];
                bfr[2*q+1][0] = r4[2]; bfr[2*q+1][1] = r4[3];
            }
            float d0[4] = {0.f, 0.f, 0.f, 0.f};
            float d1[4] = {0.f, 0.f, 0.f, 0.f};
            mma16816(d0, aff[0], bfr[0][0], bfr[0][1]);
            mma16816(d1, aff[1], bfr[1][0], bfr[1][1]);
            mma16816(d0, aff[0], bfr[2][0], bfr[2][1]);
            mma16816(d1, aff[1], bfr[3][0], bfr[3][1]);
            mma16816(d0, aff[2], bfr[0][0], bfr[0][1]);
            mma16816(d1, aff[3], bfr[1][0], bfr[1][1]);
            const int col = 8 * nt + 2 * tq;
            if (col < H) {
                const int rg = cta_base + 16 * warp + g8;
                if (rg < B) {
                    float* p0 = out + ((size_t)rg * T_STEPS + t) * H + col;
                    p0[0] = d0[0] + d1[0];
                    if (col + 1 < H) p0[1] = d0[1] + d1[1];
                }
                if (rg + 8 < B) {
                    float* p1 = out + ((size_t)(rg + 8) * T_STEPS + t) * H + col;
                    p1[0] = d0[2] + d1[2];
                    if (col + 1 < H) p1[1] = d0[3] + d1[3];
                }
            }
        }
    }
}

extern "C" void kernel_launch(void* const* d_in, const int* in_sizes, int n_in,
                              void* d_out, int out_size)
{
    const float* x   = (const float*)d_in[0];
    const float* h0  = (const float*)d_in[1];
    const float* c0  = (const float*)d_in[2];
    const float* Wih = (const float*)d_in[3];
    const float* Whh = (const float*)d_in[4];
    const float* bih = (const float*)d_in[5];
    const float* bhh = (const float*)d_in[6];
    const float* Wl  = (const float*)d_in[7];
    const float* bl  = (const float*)d_in[8];
    float* out = (float*)d_out;

    const int B = in_sizes[0] / (T_STEPS * H);   // 32768

    static bool attr_set = false;
    if (!attr_set) {
        cudaFuncSetAttribute(lstm3_hmma_kernel,
                             cudaFuncAttributeMaxDynamicSharedMemorySize, SMEM_TOTAL);
        attr_set = true;
    }

    const int grid = (B + ROWS_CTA - 1) / ROWS_CTA;   // 147
    lstm3_hmma_kernel<<<grid, THREADS, SMEM_TOTAL>>>(
        x, h0, c0, Wih, Whh, bih, bhh, Wl, bl, out, B);
}